// round 2
// baseline (speedup 1.0000x reference)
#include <cuda_runtime.h>

// ---------------- problem constants ----------------
#define IMG_H 512
#define IMG_W 512
#define OUT_H 502           // 512 - 11 + 1
#define OUT_W 502
#define NCHAN 96            // B*C = 32*3
#define NPIX_TOTAL (96.0 * 502.0 * 502.0)

// ---------------- tile geometry ----------------
#define OW_T 32             // outputs per tile (x)
#define OH_T 64             // outputs per tile (y)
#define IW_T 42             // OW_T + 10
#define IH_T 74             // OH_T + 10
#define S_STRIDE 43         // odd stride -> conflict-free LDS for input tiles
#define H_STRIDE 33         // odd stride -> conflict-free LDS/STS for intermediates
#define NTHREADS 256

#define C1_CONST 1.0e-4f    // 0.01^2
#define C2_CONST 9.0e-4f    // 0.03^2

// Gaussian window (sigma=1.5, 11 taps), normalized. constexpr device fn so that
// fully-unrolled loops fold these into FFMA immediates (imm form, rt_SMSP=1).
__device__ __forceinline__ constexpr float wt(int k) {
    return (k == 0 || k == 10) ? 0.00102838f
         : (k == 1 || k == 9)  ? 0.00759876f
         : (k == 2 || k == 8)  ? 0.03600077f
         : (k == 3 || k == 7)  ? 0.10936069f
         : (k == 4 || k == 6)  ? 0.21300554f
         :                       0.26601171f;
}

__device__ double g_accum;

__global__ void ssim_zero_kernel() { g_accum = 0.0; }

__global__ void ssim_fin_kernel(float* out) {
    out[0] = (float)(g_accum * (1.0 / NPIX_TOTAL));
}

__global__ void __launch_bounds__(NTHREADS, 2)
ssim_main_kernel(const float* __restrict__ img1, const float* __restrict__ img2) {
    extern __shared__ float smem[];
    float* s1 = smem;                          // IH_T * S_STRIDE
    float* s2 = s1 + IH_T * S_STRIDE;          // IH_T * S_STRIDE
    float* hb = s2 + IH_T * S_STRIDE;          // 5 * IH_T * H_STRIDE

    const int tid = threadIdx.x;
    const int x0g = blockIdx.x * OW_T;
    const int y0g = blockIdx.y * OH_T;
    const size_t base = (size_t)blockIdx.z * (IMG_H * IMG_W);

    // ---------------- Phase A: load input tiles (zero-fill OOB) ----------------
    for (int i = tid; i < IH_T * IW_T; i += NTHREADS) {
        int r = i / IW_T;
        int c = i - r * IW_T;
        int gy = y0g + r;
        int gx = x0g + c;
        float a = 0.0f, b = 0.0f;
        if (gy < IMG_H && gx < IMG_W) {
            size_t idx = base + (size_t)gy * IMG_W + gx;
            a = img1[idx];
            b = img2[idx];
        }
        s1[r * S_STRIDE + c] = a;
        s2[r * S_STRIDE + c] = b;
    }
    __syncthreads();

    // ---------------- Phase B: horizontal separable conv ----------------
    // Tasks: 74 rows x 4 x-strips (8 outputs each) = 296.
    // Scatter form: stream 18 inputs, accumulate into 5x8 accumulators.
    for (int t = tid; t < IH_T * 4; t += NTHREADS) {
        const int r  = t >> 2;
        const int xs = (t & 3) * 8;
        float acc[5][8];
        #pragma unroll
        for (int f = 0; f < 5; f++)
            #pragma unroll
            for (int o = 0; o < 8; o++) acc[f][o] = 0.0f;

        const float* p1 = s1 + r * S_STRIDE + xs;
        const float* p2 = s2 + r * S_STRIDE + xs;
        #pragma unroll
        for (int i = 0; i < 18; i++) {
            float a = p1[i];
            float b = p2[i];
            float aa = a * a;
            float bb = b * b;
            float ab = a * b;
            #pragma unroll
            for (int o = 0; o < 8; o++) {
                const int k = i - o;
                if (k >= 0 && k < 11) {
                    const float w = wt(k);
                    acc[0][o] += w * a;
                    acc[1][o] += w * b;
                    acc[2][o] += w * aa;
                    acc[3][o] += w * bb;
                    acc[4][o] += w * ab;
                }
            }
        }
        #pragma unroll
        for (int f = 0; f < 5; f++) {
            float* hp = hb + f * (IH_T * H_STRIDE) + r * H_STRIDE + xs;
            #pragma unroll
            for (int o = 0; o < 8; o++) hp[o] = acc[f][o];
        }
    }
    __syncthreads();

    // ---------------- Phase C: vertical conv + SSIM ----------------
    // Thread = (x = tid&31, y-strip of 8 outputs = tid>>5). Exactly 256 tasks.
    {
        const int x  = tid & 31;
        const int ys = (tid >> 5) * 8;
        float acc[5][8];
        #pragma unroll
        for (int f = 0; f < 5; f++)
            #pragma unroll
            for (int o = 0; o < 8; o++) acc[f][o] = 0.0f;

        #pragma unroll
        for (int i = 0; i < 18; i++) {
            const int r = ys + i;
            float v0 = hb[0 * (IH_T * H_STRIDE) + r * H_STRIDE + x];
            float v1 = hb[1 * (IH_T * H_STRIDE) + r * H_STRIDE + x];
            float v2 = hb[2 * (IH_T * H_STRIDE) + r * H_STRIDE + x];
            float v3 = hb[3 * (IH_T * H_STRIDE) + r * H_STRIDE + x];
            float v4 = hb[4 * (IH_T * H_STRIDE) + r * H_STRIDE + x];
            #pragma unroll
            for (int o = 0; o < 8; o++) {
                const int k = i - o;
                if (k >= 0 && k < 11) {
                    const float w = wt(k);
                    acc[0][o] += w * v0;
                    acc[1][o] += w * v1;
                    acc[2][o] += w * v2;
                    acc[3][o] += w * v3;
                    acc[4][o] += w * v4;
                }
            }
        }

        float local = 0.0f;
        const int gx = x0g + x;
        if (gx < OUT_W) {
            #pragma unroll
            for (int o = 0; o < 8; o++) {
                const int gy = y0g + ys + o;
                if (gy < OUT_H) {
                    float mu1 = acc[0][o];
                    float mu2 = acc[1][o];
                    float m11 = mu1 * mu1;
                    float m22 = mu2 * mu2;
                    float m12 = mu1 * mu2;
                    float sg1 = acc[2][o] - m11;
                    float sg2 = acc[3][o] - m22;
                    float s12 = acc[4][o] - m12;
                    float num = (2.0f * m12 + C1_CONST) * (2.0f * s12 + C2_CONST);
                    float den = (m11 + m22 + C1_CONST) * (sg1 + sg2 + C2_CONST);
                    local += num / den;
                }
            }
        }

        // ---------------- block reduce + global accumulate ----------------
        __shared__ float red[NTHREADS];
        red[tid] = local;
        __syncthreads();
        #pragma unroll
        for (int s = NTHREADS / 2; s > 0; s >>= 1) {
            if (tid < s) red[tid] += red[tid + s];
            __syncthreads();
        }
        if (tid == 0) atomicAdd(&g_accum, (double)red[0]);
    }
}

extern "C" void kernel_launch(void* const* d_in, const int* in_sizes, int n_in,
                              void* d_out, int out_size) {
    const float* img1 = (const float*)d_in[0];
    const float* img2 = (const float*)d_in[1];
    float* out = (float*)d_out;

    const size_t smem_bytes =
        (size_t)(2 * IH_T * S_STRIDE + 5 * IH_T * H_STRIDE) * sizeof(float); // ~74.3 KB
    cudaFuncSetAttribute(ssim_main_kernel,
                         cudaFuncAttributeMaxDynamicSharedMemorySize,
                         (int)smem_bytes);

    ssim_zero_kernel<<<1, 1>>>();
    dim3 grid((OUT_W + OW_T - 1) / OW_T,   // 16
              (OUT_H + OH_T - 1) / OH_T,   // 8
              NCHAN);                      // 96
    ssim_main_kernel<<<grid, NTHREADS, smem_bytes>>>(img1, img2);
    ssim_fin_kernel<<<1, 1>>>(out);
}